// round 2
// baseline (speedup 1.0000x reference)
#include <cuda_runtime.h>
#include <math.h>

// ---------------- problem constants ----------------
#define NN    30000
#define EE    300000
#define FIN   33
#define HID   132
#define HEADS 4
#define HH    (HEADS*HID)   // 528
#define GG    64
#define GFC   1024
#define OUTD  128

// ---------------- scratch (device globals; no allocation allowed) ----------------
__device__ __align__(16) float g_dis[NN];
__device__ int   g_cnt[NN];
__device__ int   g_off[NN+1];
__device__ int   g_cur[NN];
__device__ int   g_csr_src[EE];
__device__ int   g_csr_eid[EE];
__device__ __align__(16) float g_h0[NN*HID];
__device__ __align__(16) float g_x1[NN*HID];
__device__ __align__(16) float g_x2[NN*HID];
__device__ __align__(16) float g_x3[NN*HID];
__device__ __align__(16) float g_hg[NN*HH];
__device__ __align__(16) float g_es[NN*HEADS];
__device__ __align__(16) float g_ed[NN*HEADS];
__device__ __align__(16) float g_ex[EE*HEADS];
__device__ __align__(16) float g_xc[NN*HID];
__device__ __align__(16) float g_t [NN*HID];
__device__ unsigned g_pool_u[GG*HID];
__device__ __align__(16) float g_pool[GG*HID];
__device__ __align__(16) float g_hid[GG*GFC];

// ---------------- CSR build ----------------
__global__ void zero_cnt_kernel() {
    int i = blockIdx.x*blockDim.x + threadIdx.x;
    if (i < NN) g_cnt[i] = 0;
}
__global__ void hist_kernel(const int* __restrict__ ei) {
    int e = blockIdx.x*blockDim.x + threadIdx.x;
    if (e < EE) atomicAdd(&g_cnt[ei[EE + e]], 1);
}
// single-block exclusive scan over NN counts
__global__ void scan_kernel() {
    const int CH = (NN + 1023) / 1024;   // 30
    __shared__ int ssum[1024];
    int t = threadIdx.x;
    int c0 = t*CH, c1 = min(c0+CH, NN);
    int s = 0;
    for (int i = c0; i < c1; ++i) s += g_cnt[i];
    ssum[t] = s;
    __syncthreads();
    for (int d = 1; d < 1024; d <<= 1) {
        int v = (t >= d) ? ssum[t-d] : 0;
        __syncthreads();
        ssum[t] += v;
        __syncthreads();
    }
    int run = (t == 0) ? 0 : ssum[t-1];
    for (int i = c0; i < c1; ++i) { g_off[i] = run; run += g_cnt[i]; }
    if (t == 0) g_off[NN] = ssum[1023];
}
__global__ void cursor_kernel() {
    int i = blockIdx.x*blockDim.x + threadIdx.x;
    if (i < NN) g_cur[i] = g_off[i];
}
__global__ void fill_kernel(const int* __restrict__ ei) {
    int e = blockIdx.x*blockDim.x + threadIdx.x;
    if (e >= EE) return;
    int d = ei[EE + e];
    int p = atomicAdd(&g_cur[d], 1);
    g_csr_src[p] = ei[e];
    g_csr_eid[p] = e;
}
// dis[n] = rsqrt(1 + sum of incoming edge weights)    (self loop weight 1)
__global__ void deg_kernel(const float* __restrict__ ew) {
    int gw = (blockIdx.x*blockDim.x + threadIdx.x) >> 5;
    int lane = threadIdx.x & 31;
    if (gw >= NN) return;
    int b0 = g_off[gw], b1 = g_off[gw+1];
    float s = 0.f;
    for (int j = b0 + lane; j < b1; j += 32) s += ew[g_csr_eid[j]];
    #pragma unroll
    for (int o = 16; o; o >>= 1) s += __shfl_down_sync(0xffffffffu, s, o);
    if (lane == 0) g_dis[gw] = rsqrtf(1.f + s);
}

// ---------------- generic tiled fp32 GEMM:  C (+=) A[M,K] @ B[K,N] + bias ----------------
template<bool RELU, bool ACC>
__global__ __launch_bounds__(256) void gemm_kernel(
    const float* __restrict__ A, const float* __restrict__ B,
    const float* __restrict__ bias, float* __restrict__ C,
    int M, int N, int K)
{
    const int BM = 64, BN = 64, BK = 16;
    __shared__ float As[BK][BM+4];
    __shared__ float Bs[BK][BN];
    int n0 = blockIdx.x*BN, m0 = blockIdx.y*BM;
    int tid = threadIdx.x;
    int tx = tid & 15, ty = tid >> 4;
    float acc[4][4] = {};
    for (int k0 = 0; k0 < K; k0 += BK) {
        #pragma unroll
        for (int r = 0; r < 4; ++r) {
            int idx = tid + r*256;
            int i = idx >> 4, j = idx & 15;
            int gm = m0 + i, gk = k0 + j;
            As[j][i] = (gm < M && gk < K) ? A[gm*K + gk] : 0.f;
        }
        #pragma unroll
        for (int r = 0; r < 4; ++r) {
            int idx = tid + r*256;
            int j = idx >> 6, i = idx & 63;
            int gk = k0 + j, gn = n0 + i;
            Bs[j][i] = (gk < K && gn < N) ? B[gk*N + gn] : 0.f;
        }
        __syncthreads();
        #pragma unroll
        for (int k = 0; k < BK; ++k) {
            float a[4], b[4];
            #pragma unroll
            for (int i = 0; i < 4; ++i) a[i] = As[k][ty*4+i];
            #pragma unroll
            for (int j = 0; j < 4; ++j) b[j] = Bs[k][tx*4+j];
            #pragma unroll
            for (int i = 0; i < 4; ++i)
                #pragma unroll
                for (int j = 0; j < 4; ++j)
                    acc[i][j] += a[i]*b[j];
        }
        __syncthreads();
    }
    #pragma unroll
    for (int i = 0; i < 4; ++i) {
        int gm = m0 + ty*4 + i;
        if (gm >= M) continue;
        #pragma unroll
        for (int j = 0; j < 4; ++j) {
            int gn = n0 + tx*4 + j;
            if (gn >= N) continue;
            float v = acc[i][j] + (bias ? bias[gn] : 0.f);
            if (ACC) v += C[gm*N + gn];
            if (RELU) v = fmaxf(v, 0.f);
            C[gm*N + gn] = v;
        }
    }
}

// ---------------- GCN aggregation (CSR, one block per node) ----------------
__global__ void gcn_agg_kernel(const float* __restrict__ ew, const float* __restrict__ bias) {
    int n = blockIdx.x, c = threadIdx.x;   // blockDim = 132
    float dn = g_dis[n];
    float acc = bias[c] + dn*dn*g_h0[n*HID + c];
    int b0 = g_off[n], b1 = g_off[n+1];
    for (int j = b0; j < b1; ++j) {
        int s = g_csr_src[j];
        int e = g_csr_eid[j];
        float norm = g_dis[s] * ew[e] * dn;
        acc += norm * g_h0[s*HID + c];
    }
    g_x1[n*HID + c] = fmaxf(acc, 0.f);
}

// ---------------- GAT attention scores ----------------
__global__ void scores_kernel(const float* __restrict__ asrc, const float* __restrict__ adst) {
    int w = threadIdx.x >> 5, lane = threadIdx.x & 31;
    int n = blockIdx.x, h = w;              // blockDim 128, 4 warps = 4 heads
    const float* row = g_hg + n*HH + h*HID;
    float s1 = 0.f, s2 = 0.f;
    for (int c = lane; c < HID; c += 32) {
        float v = row[c];
        s1 += v*asrc[h*HID + c];
        s2 += v*adst[h*HID + c];
    }
    #pragma unroll
    for (int o = 16; o; o >>= 1) {
        s1 += __shfl_down_sync(0xffffffffu, s1, o);
        s2 += __shfl_down_sync(0xffffffffu, s2, o);
    }
    if (lane == 0) { g_es[n*4 + h] = s1; g_ed[n*4 + h] = s2; }
}

__device__ __forceinline__ float lrelu02(float v) { return v > 0.f ? v : 0.2f*v; }

// per-edge softmax numerators (max-shift omitted: |e| << 1, mathematically identical alpha)
__global__ void exp_edge_kernel(const int* __restrict__ ei) {
    int e = blockIdx.x*blockDim.x + threadIdx.x;
    if (e >= EE) return;
    int s = ei[e], d = ei[EE + e];
    float4 a = *(const float4*)(g_es + s*4);
    float4 b = *(const float4*)(g_ed + d*4);
    float4 r;
    r.x = expf(lrelu02(a.x + b.x));
    r.y = expf(lrelu02(a.y + b.y));
    r.z = expf(lrelu02(a.z + b.z));
    r.w = expf(lrelu02(a.w + b.w));
    ((float4*)g_ex)[e] = r;
}

// ---------------- GAT aggregation (CSR, one block per node, mean-over-heads folded) ----------------
__global__ void gat_agg_kernel(const float* __restrict__ bias, int relu) {
    int n = blockIdx.x, c = threadIdx.x;    // blockDim = 132
    __shared__ float sw[4];    // 0.25 * self_ex / denom
    __shared__ float sinv[4];  // 0.25 / denom
    int b0 = g_off[n], b1 = g_off[n+1];
    if (c < 4) {
        int h = c;
        float ax = expf(lrelu02(g_es[n*4 + h] + g_ed[n*4 + h]));
        float dsum = ax;
        for (int j = b0; j < b1; ++j) dsum += g_ex[g_csr_eid[j]*4 + h];
        float inv = 0.25f / dsum;
        sw[h] = ax*inv;
        sinv[h] = inv;
    }
    __syncthreads();
    const float* hn = g_hg + n*HH;
    float acc = bias[c] + sw[0]*hn[c] + sw[1]*hn[HID + c]
                        + sw[2]*hn[2*HID + c] + sw[3]*hn[3*HID + c];
    float i0 = sinv[0], i1 = sinv[1], i2 = sinv[2], i3 = sinv[3];
    for (int j = b0; j < b1; ++j) {
        int s = g_csr_src[j];
        int e = g_csr_eid[j];
        float4 x4 = *(const float4*)(g_ex + e*4);
        const float* hs = g_hg + s*HH;
        acc += (x4.x*i0)*hs[c] + (x4.y*i1)*hs[HID + c]
             + (x4.z*i2)*hs[2*HID + c] + (x4.w*i3)*hs[3*HID + c];
    }
    if (relu) acc = fmaxf(acc, 0.f);
    g_xc[n*HID + c] = acc;
}

// ---------------- gated fusion ----------------
__global__ void gate_kernel(const float* __restrict__ pro,
                            const float* __restrict__ xp, float* __restrict__ out) {
    int i = blockIdx.x*blockDim.x + threadIdx.x;
    if (i >= NN*HID) return;
    int c = i % HID;
    float z = 1.f / (1.f + expf(-(g_t[i] + pro[c])));
    out[i] = z*g_xc[i] + (1.f - z)*xp[i];
}

// ---------------- global max pool ----------------
__device__ __forceinline__ unsigned fmap(float f) {
    unsigned u = __float_as_uint(f);
    return (u & 0x80000000u) ? ~u : (u | 0x80000000u);
}
__global__ void pool_init_kernel() {
    int i = blockIdx.x*blockDim.x + threadIdx.x;
    if (i < GG*HID) g_pool_u[i] = 0u;
}
__global__ void pool_max_kernel(const int* __restrict__ batch) {
    int i = blockIdx.x*blockDim.x + threadIdx.x;
    if (i >= NN*HID) return;
    int n = i / HID, c = i % HID;
    int gidx = batch[n];
    atomicMax(&g_pool_u[gidx*HID + c], fmap(g_x3[i]));
}
__global__ void pool_decode_kernel() {
    int i = blockIdx.x*blockDim.x + threadIdx.x;
    if (i >= GG*HID) return;
    unsigned u = g_pool_u[i];
    g_pool[i] = (u & 0x80000000u) ? __uint_as_float(u ^ 0x80000000u)
                                  : __uint_as_float(~u);
}

// ---------------- launch ----------------
static inline dim3 gemm_grid(int M, int N) { return dim3((N + 63)/64, (M + 63)/64); }

static float* devptr(const void* sym) {
    void* p = nullptr;
    cudaGetSymbolAddress(&p, sym);   // not needed; placeholder (unused)
    return (float*)p;
}

extern "C" void kernel_launch(void* const* d_in, const int* in_sizes, int n_in,
                              void* d_out, int out_size) {
    const float* x        = (const float*)d_in[0];
    const int*   ei       = (const int*)  d_in[1];
    const float* ew       = (const float*)d_in[2];
    const int*   batch    = (const int*)  d_in[3];
    const float* W_gcn    = (const float*)d_in[4];
    const float* b_gcn    = (const float*)d_in[5];
    const float* W_gat1   = (const float*)d_in[6];
    const float* a_src1   = (const float*)d_in[7];
    const float* a_dst1   = (const float*)d_in[8];
    const float* b_gat1   = (const float*)d_in[9];
    const float* W_gat2   = (const float*)d_in[10];
    const float* a_src2   = (const float*)d_in[11];
    const float* a_dst2   = (const float*)d_in[12];
    const float* b_gat2   = (const float*)d_in[13];
    const float* W_fc1    = (const float*)d_in[14];
    const float* b_fc1    = (const float*)d_in[15];
    const float* W_fc2    = (const float*)d_in[16];
    const float* b_fc2    = (const float*)d_in[17];
    const float* pro_bias = (const float*)d_in[18];
    const float* W_g1     = (const float*)d_in[19];
    const float* b_g1     = (const float*)d_in[20];
    const float* W_g2     = (const float*)d_in[21];
    const float* b_g2     = (const float*)d_in[22];
    float* out = (float*)d_out;

    // device-global scratch pointers
    float *p_h0, *p_x1, *p_x2, *p_x3, *p_hg, *p_xc, *p_t, *p_pool, *p_hid;
    cudaGetSymbolAddress((void**)&p_h0,  g_h0);
    cudaGetSymbolAddress((void**)&p_x1,  g_x1);
    cudaGetSymbolAddress((void**)&p_x2,  g_x2);
    cudaGetSymbolAddress((void**)&p_x3,  g_x3);
    cudaGetSymbolAddress((void**)&p_hg,  g_hg);
    cudaGetSymbolAddress((void**)&p_xc,  g_xc);
    cudaGetSymbolAddress((void**)&p_t,   g_t);
    cudaGetSymbolAddress((void**)&p_pool,g_pool);
    cudaGetSymbolAddress((void**)&p_hid, g_hid);

    const int TB = 256;
    // ---- CSR build (by dst), reused by all aggregation passes ----
    zero_cnt_kernel<<<(NN+TB-1)/TB, TB>>>();
    hist_kernel<<<(EE+TB-1)/TB, TB>>>(ei);
    scan_kernel<<<1, 1024>>>();
    cursor_kernel<<<(NN+TB-1)/TB, TB>>>();
    fill_kernel<<<(EE+TB-1)/TB, TB>>>(ei);
    deg_kernel<<<(NN*32+TB-1)/TB, TB>>>(ew);

    // ---- layer 0: GCN + relu ----
    gemm_kernel<false,false><<<gemm_grid(NN,HID), 256>>>(x, W_gcn, nullptr, p_h0, NN, HID, FIN);
    gcn_agg_kernel<<<NN, HID>>>(ew, b_gcn);

    // ---- layer 1: GAT + relu, gated fusion with x1 ----
    gemm_kernel<false,false><<<gemm_grid(NN,HH), 256>>>(p_x1, W_gat1, nullptr, p_hg, NN, HH, HID);
    scores_kernel<<<NN, 128>>>(a_src1, a_dst1);
    exp_edge_kernel<<<(EE+TB-1)/TB, TB>>>(ei);
    gat_agg_kernel<<<NN, HID>>>(b_gat1, 1);
    gemm_kernel<false,false><<<gemm_grid(NN,HID), 256>>>(p_xc, W_fc1, b_fc1, p_t, NN, HID, HID);
    gemm_kernel<false,true ><<<gemm_grid(NN,HID), 256>>>(p_x1, W_fc2, b_fc2, p_t, NN, HID, HID);
    gate_kernel<<<(NN*HID+TB-1)/TB, TB>>>(pro_bias, p_x1, p_x2);

    // ---- layer 2: GAT (no relu), gated fusion with x2 ----
    gemm_kernel<false,false><<<gemm_grid(NN,HH), 256>>>(p_x2, W_gat2, nullptr, p_hg, NN, HH, HID);
    scores_kernel<<<NN, 128>>>(a_src2, a_dst2);
    exp_edge_kernel<<<(EE+TB-1)/TB, TB>>>(ei);
    gat_agg_kernel<<<NN, HID>>>(b_gat2, 0);
    gemm_kernel<false,false><<<gemm_grid(NN,HID), 256>>>(p_xc, W_fc1, b_fc1, p_t, NN, HID, HID);
    gemm_kernel<false,true ><<<gemm_grid(NN,HID), 256>>>(p_x2, W_fc2, b_fc2, p_t, NN, HID, HID);
    gate_kernel<<<(NN*HID+TB-1)/TB, TB>>>(pro_bias, p_x2, p_x3);

    // ---- global max pool + MLP head ----
    pool_init_kernel<<<(GG*HID+TB-1)/TB, TB>>>();
    pool_max_kernel<<<(NN*HID+TB-1)/TB, TB>>>(batch);
    pool_decode_kernel<<<(GG*HID+TB-1)/TB, TB>>>();
    gemm_kernel<true ,false><<<gemm_grid(GG,GFC ), 256>>>(p_pool, W_g1, b_g1, p_hid, GG, GFC, HID);
    gemm_kernel<false,false><<<gemm_grid(GG,OUTD), 256>>>(p_hid, W_g2, b_g2, out, GG, OUTD, GFC);
}

// round 4
// speedup vs baseline: 1.0471x; 1.0471x over previous
#include <cuda_runtime.h>
#include <cuda_bf16.h>
#include <math.h>
#include <stdint.h>

// ---------------- problem constants ----------------
#define NN    30000
#define EE    300000
#define FIN   33
#define HID   132
#define HEADS 4
#define HH    (HEADS*HID)   // 528
#define GG    64
#define GFC   1024
#define OUTD  128

// ---------------- scratch (device globals; no allocation allowed) ----------------
__device__ __align__(16) float g_dis[NN];
__device__ int   g_cnt[NN];
__device__ int   g_off[NN+1];
__device__ int   g_cur[NN];
__device__ int   g_csr_src[EE];
__device__ int   g_csr_eid[EE];
__device__ __align__(16) float g_h0[NN*HID];
__device__ __align__(16) float g_x1[NN*HID];
__device__ __align__(16) float g_x2[NN*HID];
__device__ __align__(16) float g_x3[NN*HID];
__device__ __align__(16) float g_hg[NN*HH];
__device__ __align__(16) float g_es[NN*HEADS];
__device__ __align__(16) float g_ed[NN*HEADS];
__device__ __align__(16) float g_ex[EE*HEADS];
__device__ __align__(16) float g_xc[NN*HID];
__device__ __align__(16) float g_t [NN*HID];
__device__ unsigned g_pool_u[GG*HID];
__device__ __align__(16) float g_pool[GG*HID];
__device__ __align__(16) float g_hid[GG*GFC];
// bf16 weights (hi/lo), stored transposed [Npad][K] (k contiguous)
__device__ __align__(16) __nv_bfloat16 g_bhi[576*HID];
__device__ __align__(16) __nv_bfloat16 g_blo[576*HID];
__device__ __align__(16) __nv_bfloat16 g_bhi_gcn[192*FIN];
__device__ __align__(16) __nv_bfloat16 g_blo_gcn[192*FIN];
__device__ __align__(16) __nv_bfloat16 g_bhi_fc[192*264];
__device__ __align__(16) __nv_bfloat16 g_blo_fc[192*264];
__device__ float g_bias_fc[HID];

// ---------------- CSR build ----------------
__global__ void zero_cnt_kernel() {
    int i = blockIdx.x*blockDim.x + threadIdx.x;
    if (i < NN) g_cnt[i] = 0;
}
__global__ void hist_kernel(const int* __restrict__ ei) {
    int e = blockIdx.x*blockDim.x + threadIdx.x;
    if (e < EE) atomicAdd(&g_cnt[ei[EE + e]], 1);
}
__global__ void scan_kernel() {
    const int CH = (NN + 1023) / 1024;
    __shared__ int ssum[1024];
    int t = threadIdx.x;
    int c0 = t*CH, c1 = min(c0+CH, NN);
    int s = 0;
    for (int i = c0; i < c1; ++i) s += g_cnt[i];
    ssum[t] = s;
    __syncthreads();
    for (int d = 1; d < 1024; d <<= 1) {
        int v = (t >= d) ? ssum[t-d] : 0;
        __syncthreads();
        ssum[t] += v;
        __syncthreads();
    }
    int run = (t == 0) ? 0 : ssum[t-1];
    for (int i = c0; i < c1; ++i) { g_off[i] = run; run += g_cnt[i]; }
    if (t == 0) g_off[NN] = ssum[1023];
}
__global__ void cursor_kernel() {
    int i = blockIdx.x*blockDim.x + threadIdx.x;
    if (i < NN) g_cur[i] = g_off[i];
}
__global__ void fill_kernel(const int* __restrict__ ei) {
    int e = blockIdx.x*blockDim.x + threadIdx.x;
    if (e >= EE) return;
    int d = ei[EE + e];
    int p = atomicAdd(&g_cur[d], 1);
    g_csr_src[p] = ei[e];
    g_csr_eid[p] = e;
}
__global__ void deg_kernel(const float* __restrict__ ew) {
    int gw = (blockIdx.x*blockDim.x + threadIdx.x) >> 5;
    int lane = threadIdx.x & 31;
    if (gw >= NN) return;
    int b0 = g_off[gw], b1 = g_off[gw+1];
    float s = 0.f;
    for (int j = b0 + lane; j < b1; j += 32) s += ew[g_csr_eid[j]];
    #pragma unroll
    for (int o = 16; o; o >>= 1) s += __shfl_down_sync(0xffffffffu, s, o);
    if (lane == 0) g_dis[gw] = rsqrtf(1.f + s);
}

// ---------------- weight conversions (fp32 -> bf16 hi/lo, transposed) ----------------
__device__ __forceinline__ void split_bf(float v, __nv_bfloat16& h, __nv_bfloat16& l) {
    h = __float2bfloat16(v);
    l = __float2bfloat16(v - __bfloat162float(h));
}
// W [K, Nreal] -> B [Npad][K]
__global__ void cvt_W_kernel(const float* __restrict__ W,
                             __nv_bfloat16* __restrict__ bh, __nv_bfloat16* __restrict__ bl,
                             int K, int Nreal, int Npad) {
    int i = blockIdx.x*blockDim.x + threadIdx.x;
    if (i >= Npad*K) return;
    int n = i / K, k = i % K;
    float v = (n < Nreal) ? W[k*Nreal + n] : 0.f;
    split_bf(v, bh[i], bl[i]);
}
// fused gate weights: rows 0..131 from W_fc1, 132..263 from W_fc2 -> [192][264]
__global__ void cvt_Wfc_kernel(const float* __restrict__ W1, const float* __restrict__ W2) {
    int i = blockIdx.x*blockDim.x + threadIdx.x;
    if (i >= 192*264) return;
    int n = i / 264, k = i % 264;
    float v = 0.f;
    if (n < HID) v = (k < HID) ? W1[k*HID + n] : W2[(k-HID)*HID + n];
    split_bf(v, g_bhi_fc[i], g_blo_fc[i]);
}
__global__ void bias_fc_kernel(const float* __restrict__ b1, const float* __restrict__ b2,
                               const float* __restrict__ pro) {
    int c = threadIdx.x;
    if (c < HID) g_bias_fc[c] = b1[c] + b2[c] + pro[c];
}

// ---------------- HMMA bf16 hi/lo GEMM ----------------
// C[M,Nreal] = A[M,K] @ B[Npad][K]^T, A fp32 (optionally concat A1|A2 split at 132)
// block tile 128x64, BK=32, 8 warps (4M x 2N), warp tile 32x32
#define AS 40   // smem row stride in bf16 elems (80B: conflict-free for 8-row frag columns)

__device__ __forceinline__ void mma16816(float* d, const uint32_t* a, const uint32_t* b) {
    asm volatile("mma.sync.aligned.m16n8k16.row.col.f32.bf16.bf16.f32 "
        "{%0,%1,%2,%3}, {%4,%5,%6,%7}, {%8,%9}, {%0,%1,%2,%3};"
        : "+f"(d[0]), "+f"(d[1]), "+f"(d[2]), "+f"(d[3])
        : "r"(a[0]), "r"(a[1]), "r"(a[2]), "r"(a[3]), "r"(b[0]), "r"(b[1]));
}
__device__ __forceinline__ uint32_t pack_hi(float x, float y, float& lx, float& ly) {
    __nv_bfloat16 hx = __float2bfloat16(x);
    __nv_bfloat16 hy = __float2bfloat16(y);
    lx = x - __bfloat162float(hx);
    ly = y - __bfloat162float(hy);
    __nv_bfloat162 t; t.x = hx; t.y = hy;
    return *(uint32_t*)&t;
}
__device__ __forceinline__ uint32_t pack_lo(float lx, float ly) {
    __nv_bfloat162 t; t.x = __float2bfloat16(lx); t.y = __float2bfloat16(ly);
    return *(uint32_t*)&t;
}

__global__ __launch_bounds__(256) void hmma_gemm_kernel(
    const float* __restrict__ A1, const float* __restrict__ A2,  // A2: second half of concat (or null)
    const __nv_bfloat16* __restrict__ Bh, const __nv_bfloat16* __restrict__ Bl,
    const float* __restrict__ bias, float* __restrict__ C,
    int M, int Nreal, int K)
{
    __shared__ __align__(16) uint16_t sAh[128*AS];
    __shared__ __align__(16) uint16_t sAl[128*AS];
    __shared__ __align__(16) uint16_t sBh[64*AS];
    __shared__ __align__(16) uint16_t sBl[64*AS];

    int tid = threadIdx.x, lane = tid & 31, wid = tid >> 5;
    int warpM = wid & 3, warpN = wid >> 2;
    int m0 = blockIdx.y * 128;
    int n0 = blockIdx.x * 64;

    float acc[2][4][4];
    #pragma unroll
    for (int i = 0; i < 2; ++i)
        #pragma unroll
        for (int j = 0; j < 4; ++j)
            #pragma unroll
            for (int q = 0; q < 4; ++q) acc[i][j][q] = 0.f;

    const bool kEven = ((K & 1) == 0);
    int ktiles = (K + 31) / 32;

    for (int kt = 0; kt < ktiles; ++kt) {
        int k0 = kt * 32;
        // ---- load A tile (fp32 -> bf16 hi/lo) ----
        if (kEven) {
            #pragma unroll
            for (int r = 0; r < 8; ++r) {
                int i = tid + r*256;              // 128*16 float2 slots
                int row = i >> 4, p = i & 15;
                int gm = m0 + row, gk = k0 + 2*p;
                float2 v = make_float2(0.f, 0.f);
                if (gm < M && gk < K) {
                    if (!A2 || gk + 1 < HID) v = *(const float2*)(A1 + gm*HID + gk);
                    else v = *(const float2*)(A2 + gm*HID + (gk - HID));
                }
                float lx, ly;
                uint32_t h = pack_hi(v.x, v.y, lx, ly);
                uint32_t l = pack_lo(lx, ly);
                ((uint32_t*)sAh)[row*20 + p] = h;
                ((uint32_t*)sAl)[row*20 + p] = l;
            }
        } else {
            #pragma unroll
            for (int r = 0; r < 8; ++r) {
                int i = tid + r*256;
                int row = i >> 4, p = i & 15;
                int gm = m0 + row, gk = k0 + 2*p;
                float x = 0.f, y = 0.f;
                if (gm < M) {
                    if (gk < K)     x = A1[gm*K + gk];
                    if (gk + 1 < K) y = A1[gm*K + gk + 1];
                }
                float lx, ly;
                uint32_t h = pack_hi(x, y, lx, ly);
                uint32_t l = pack_lo(lx, ly);
                ((uint32_t*)sAh)[row*20 + p] = h;
                ((uint32_t*)sAl)[row*20 + p] = l;
            }
        }
        // ---- load B tile (bf16, [n][k] k-contiguous) ----
        if (kEven) {
            #pragma unroll
            for (int r = 0; r < 4; ++r) {
                int i = tid + r*256;              // 64*16 u32 slots
                int row = i >> 4, p = i & 15;
                int gk = k0 + 2*p;
                uint32_t vh = 0, vl = 0;
                if (gk < K) {
                    int go = (n0 + row)*K + gk;
                    vh = *(const uint32_t*)(Bh + go);
                    vl = *(const uint32_t*)(Bl + go);
                }
                ((uint32_t*)sBh)[row*20 + p] = vh;
                ((uint32_t*)sBl)[row*20 + p] = vl;
            }
        } else {
            #pragma unroll
            for (int r = 0; r < 4; ++r) {
                int i = tid + r*256;
                int row = i >> 4, p = i & 15;
                int gk = k0 + 2*p;
                __nv_bfloat16 z = __float2bfloat16(0.f);
                __nv_bfloat16 hx = z, hy = z, lx = z, ly = z;
                int go = (n0 + row)*K;
                if (gk < K)     { hx = Bh[go + gk];     lx = Bl[go + gk]; }
                if (gk + 1 < K) { hy = Bh[go + gk + 1]; ly = Bl[go + gk + 1]; }
                __nv_bfloat162 th; th.x = hx; th.y = hy;
                __nv_bfloat162 tl; tl.x = lx; tl.y = ly;
                ((uint32_t*)sBh)[row*20 + p] = *(uint32_t*)&th;
                ((uint32_t*)sBl)[row*20 + p] = *(uint32_t*)&tl;
            }
        }
        __syncthreads();

        // ---- compute: two k16 steps ----
        const uint32_t* Ah32 = (const uint32_t*)sAh;
        const uint32_t* Al32 = (const uint32_t*)sAl;
        const uint32_t* Bh32 = (const uint32_t*)sBh;
        const uint32_t* Bl32 = (const uint32_t*)sBl;
        int gr = lane >> 2, gc = lane & 3;
        #pragma unroll
        for (int kk = 0; kk < 2; ++kk) {
            int cbase = kk*8 + gc;               // u32 col index (k/2)
            uint32_t ah[2][4], al[2][4];
            #pragma unroll
            for (int mt = 0; mt < 2; ++mt) {
                int r0 = warpM*32 + mt*16 + gr;
                ah[mt][0] = Ah32[r0*20 + cbase];
                ah[mt][1] = Ah32[(r0+8)*20 + cbase];
                ah[mt][2] = Ah32[r0*20 + cbase + 4];
                ah[mt][3] = Ah32[(r0+8)*20 + cbase + 4];
                al[mt][0] = Al32[r0*20 + cbase];
                al[mt][1] = Al32[(r0+8)*20 + cbase];
                al[mt][2] = Al32[r0*20 + cbase + 4];
                al[mt][3] = Al32[(r0+8)*20 + cbase + 4];
            }
            uint32_t bh[4][2], bl[4][2];
            #pragma unroll
            for (int nt = 0; nt < 4; ++nt) {
                int rn = warpN*32 + nt*8 + gr;
                bh[nt][0] = Bh32[rn*20 + cbase];
                bh[nt][1] = Bh32[rn*20 + cbase + 4];
                bl[nt][0] = Bl32[rn*20 + cbase];
                bl[nt][1] = Bl32[rn*20 + cbase + 4];
            }
            #pragma unroll
            for (int mt = 0; mt < 2; ++mt)
                #pragma unroll
                for (int nt = 0; nt < 4; ++nt) {
                    mma16816(acc[mt][nt], ah[mt], bh[nt]);
                    mma16816(acc[mt][nt], ah[mt], bl[nt]);
                    mma16816(acc[mt][nt], al[mt], bh[nt]);
                }
        }
        __syncthreads();
    }

    // ---- epilogue ----
    int gr = lane >> 2, gc2 = 2*(lane & 3);
    #pragma unroll
    for (int mt = 0; mt < 2; ++mt) {
        #pragma unroll
        for (int nt = 0; nt < 4; ++nt) {
            int n = n0 + warpN*32 + nt*8 + gc2;
            if (n >= Nreal) continue;
            float bx = bias ? bias[n] : 0.f;
            float by = bias ? bias[n+1] : 0.f;
            int m = m0 + warpM*32 + mt*16 + gr;
            if (m < M) {
                float2 v = make_float2(acc[mt][nt][0] + bx, acc[mt][nt][1] + by);
                *(float2*)(C + (size_t)m*Nreal + n) = v;
            }
            if (m + 8 < M) {
                float2 v = make_float2(acc[mt][nt][2] + bx, acc[mt][nt][3] + by);
                *(float2*)(C + (size_t)(m+8)*Nreal + n) = v;
            }
        }
    }
}

// ---------------- small SIMT GEMM (head only) ----------------
template<bool RELU>
__global__ __launch_bounds__(256) void gemm_kernel(
    const float* __restrict__ A, const float* __restrict__ B,
    const float* __restrict__ bias, float* __restrict__ C,
    int M, int N, int K)
{
    const int BM = 64, BN = 64, BK = 16;
    __shared__ float As[BK][BM+4];
    __shared__ float Bs[BK][BN];
    int n0 = blockIdx.x*BN, m0 = blockIdx.y*BM;
    int tid = threadIdx.x;
    int tx = tid & 15, ty = tid >> 4;
    float acc[4][4] = {};
    for (int k0 = 0; k0 < K; k0 += BK) {
        #pragma unroll
        for (int r = 0; r < 4; ++r) {
            int idx = tid + r*256;
            int i = idx >> 4, j = idx & 15;
            int gm = m0 + i, gk = k0 + j;
            As[j][i] = (gm < M && gk < K) ? A[gm*K + gk] : 0.f;
        }
        #pragma unroll
        for (int r = 0; r < 4; ++r) {
            int idx = tid + r*256;
            int j = idx >> 6, i = idx & 63;
            int gk = k0 + j, gn = n0 + i;
            Bs[j][i] = (gk < K && gn < N) ? B[gk*N + gn] : 0.f;
        }
        __syncthreads();
        #pragma unroll
        for (int k = 0; k < BK; ++k) {
            float a[4], b[4];
            #pragma unroll
            for (int i = 0; i < 4; ++i) a[i] = As[k][ty*4+i];
            #pragma unroll
            for (int j = 0; j < 4; ++j) b[j] = Bs[k][tx*4+j];
            #pragma unroll
            for (int i = 0; i < 4; ++i)
                #pragma unroll
                for (int j = 0; j < 4; ++j)
                    acc[i][j] += a[i]*b[j];
        }
        __syncthreads();
    }
    #pragma unroll
    for (int i = 0; i < 4; ++i) {
        int gm = m0 + ty*4 + i;
        if (gm >= M) continue;
        #pragma unroll
        for (int j = 0; j < 4; ++j) {
            int gn = n0 + tx*4 + j;
            if (gn >= N) continue;
            float v = acc[i][j] + (bias ? bias[gn] : 0.f);
            if (RELU) v = fmaxf(v, 0.f);
            C[gm*N + gn] = v;
        }
    }
}

// ---------------- GCN aggregation ----------------
__global__ void gcn_agg_kernel(const float* __restrict__ ew, const float* __restrict__ bias) {
    int n = blockIdx.x, c = threadIdx.x;
    float dn = g_dis[n];
    float acc = bias[c] + dn*dn*g_h0[n*HID + c];
    int b0 = g_off[n], b1 = g_off[n+1];
    for (int j = b0; j < b1; ++j) {
        int s = g_csr_src[j];
        int e = g_csr_eid[j];
        float norm = g_dis[s] * ew[e] * dn;
        acc += norm * g_h0[s*HID + c];
    }
    g_x1[n*HID + c] = fmaxf(acc, 0.f);
}

// ---------------- GAT attention ----------------
__global__ void scores_kernel(const float* __restrict__ asrc, const float* __restrict__ adst) {
    int w = threadIdx.x >> 5, lane = threadIdx.x & 31;
    int n = blockIdx.x, h = w;
    const float* row = g_hg + n*HH + h*HID;
    float s1 = 0.f, s2 = 0.f;
    for (int c = lane; c < HID; c += 32) {
        float v = row[c];
        s1 += v*asrc[h*HID + c];
        s2 += v*adst[h*HID + c];
    }
    #pragma unroll
    for (int o = 16; o; o >>= 1) {
        s1 += __shfl_down_sync(0xffffffffu, s1, o);
        s2 += __shfl_down_sync(0xffffffffu, s2, o);
    }
    if (lane == 0) { g_es[n*4 + h] = s1; g_ed[n*4 + h] = s2; }
}

__device__ __forceinline__ float lrelu02(float v) { return v > 0.f ? v : 0.2f*v; }

__global__ void exp_edge_kernel(const int* __restrict__ ei) {
    int e = blockIdx.x*blockDim.x + threadIdx.x;
    if (e >= EE) return;
    int s = ei[e], d = ei[EE + e];
    float4 a = *(const float4*)(g_es + s*4);
    float4 b = *(const float4*)(g_ed + d*4);
    float4 r;
    r.x = expf(lrelu02(a.x + b.x));
    r.y = expf(lrelu02(a.y + b.y));
    r.z = expf(lrelu02(a.z + b.z));
    r.w = expf(lrelu02(a.w + b.w));
    ((float4*)g_ex)[e] = r;
}

__global__ void gat_agg_kernel(const float* __restrict__ bias, int relu) {
    int n = blockIdx.x, c = threadIdx.x;
    __shared__ float sw[4];
    __shared__ float sinv[4];
    int b0 = g_off[n], b1 = g_off[n+1];
    if (c < 4) {
        int h = c;
        float ax = expf(lrelu02(g_es[n*4 + h] + g_ed[n*4 + h]));
        float dsum = ax;
        for (int j = b0; j < b1; ++j) dsum += g_ex[g_csr_eid[j]*4 + h];
        float inv = 0.25f / dsum;
        sw[h] = ax*inv;
        sinv[h] = inv;
    }
    __syncthreads();
    const float* hn = g_hg + n*HH;
    float acc = bias[c] + sw[0]*hn[c] + sw[1]*hn[HID + c]
                        + sw[2]*hn[2*HID + c] + sw[3]*hn[3*HID + c];
    float i0 = sinv[0], i1 = sinv[1], i2 = sinv[2], i3 = sinv[3];
    for (int j = b0; j < b1; ++j) {
        int s = g_csr_src[j];
        int e = g_csr_eid[j];
        float4 x4 = *(const float4*)(g_ex + e*4);
        const float* hs = g_hg + s*HH;
        acc += (x4.x*i0)*hs[c] + (x4.y*i1)*hs[HID + c]
             + (x4.z*i2)*hs[2*HID + c] + (x4.w*i3)*hs[3*HID + c];
    }
    if (relu) acc = fmaxf(acc, 0.f);
    g_xc[n*HID + c] = acc;
}

// ---------------- gated fusion (all biases pre-folded into g_t) ----------------
__global__ void gate_kernel(const float* __restrict__ xp, float* __restrict__ out) {
    int i = blockIdx.x*blockDim.x + threadIdx.x;
    if (i >= NN*HID) return;
    float z = 1.f / (1.f + expf(-g_t[i]));
    out[i] = z*g_xc[i] + (1.f - z)*xp[i];
}

// ---------------- global max pool ----------------
__device__ __forceinline__ unsigned fmap(float f) {
    unsigned u = __float_as_uint(f);
    return (u & 0x80000000u) ? ~u : (u | 0x80000000u);
}
__global__ void pool_init_kernel() {
    int i = blockIdx.x*blockDim.x + threadIdx.x;
    if (i < GG*HID) g_pool_u[i] = 0u;
}
__global__ void pool_max_kernel(const int* __restrict__ batch) {
    int i = blockIdx.x*blockDim.x + threadIdx.x;
    if (i >= NN*HID) return;
    int n = i / HID, c = i % HID;
    int gidx = batch[n];
    atomicMax(&g_pool_u[gidx*HID + c], fmap(g_x3[i]));
}
__global__ void pool_decode_kernel() {
    int i = blockIdx.x*blockDim.x + threadIdx.x;
    if (i >= GG*HID) return;
    unsigned u = g_pool_u[i];
    g_pool[i] = (u & 0x80000000u) ? __uint_as_float(u ^ 0x80000000u)
                                  : __uint_as_float(~u);
}

// ---------------- launch ----------------
static inline dim3 gemm_grid(int M, int N) { return dim3((N + 63)/64, (M + 63)/64); }

extern "C" void kernel_launch(void* const* d_in, const int* in_sizes, int n_in,
                              void* d_out, int out_size) {
    const float* x        = (const float*)d_in[0];
    const int*   ei       = (const int*)  d_in[1];
    const float* ew       = (const float*)d_in[2];
    const int*   batch    = (const int*)  d_in[3];
    const float* W_gcn    = (const float*)d_in[4];
    const float* b_gcn    = (const float*)d_in[5];
    const float* W_gat1   = (const float*)d_in[6];
    const float* a_src1   = (const float*)d_in[7];
    const float* a_dst1   = (const float*)d_in[8];
    const float* b_gat1   = (const float*)d_in[9];
    const float* W_gat2   = (const float*)d_in[10];
    const float* a_src2   = (const float*)d_in[11];
    const float* a_dst2   = (const float*)d_in[12];
    const float* b_gat2   = (const float*)d_in[13];
    const float* W_fc1    = (const float*)d_in[14];
    const float* b_fc1    = (const float*)d_in[15];
    const float* W_fc2    = (const float*)d_in[16];
    const float* b_fc2    = (const float*)d_in[17];
    const float* pro_bias = (const float*)d_in[18];
    const float* W_g1     = (const float*)d_in[19];
    const float* b_g1     = (const float*)d_in[20];
    const float* W_g2     = (const float*)d_in[21];
    const float* b_g2     = (const float*)d_in[22];
    float* out = (float*)d_out;

    float *p_h0, *p_x1, *p_x2, *p_x3, *p_hg, *p_xc, *p_t, *p_pool, *p_hid, *p_bias_fc;
    __nv_bfloat16 *p_bhi, *p_blo, *p_bhi_gcn, *p_blo_gcn, *p_bhi_fc, *p_blo_fc;
    cudaGetSymbolAddress((void**)&p_h0,  g_h0);
    cudaGetSymbolAddress((void**)&p_x1,  g_x1);
    cudaGetSymbolAddress((void**)&p_x2,  g_x2);
    cudaGetSymbolAddress((void**)&p_x3,  g_x3);
    cudaGetSymbolAddress((void**)&p_hg,  g_hg);
    cudaGetSymbolAddress((void**)&p_xc,  g_xc);
    cudaGetSymbolAddress((void**)&p_t,   g_t);
    cudaGetSymbolAddress((void**)&p_pool,g_pool);
    cudaGetSymbolAddress((void**)&p_hid, g_hid);
    cudaGetSymbolAddress((void**)&p_bias_fc, g_bias_fc);
    cudaGetSymbolAddress((void**)&p_bhi, g_bhi);
    cudaGetSymbolAddress((void**)&p_blo, g_blo);
    cudaGetSymbolAddress((void**)&p_bhi_gcn, g_bhi_gcn);
    cudaGetSymbolAddress((void**)&p_blo_gcn, g_blo_gcn);
    cudaGetSymbolAddress((void**)&p_bhi_fc, g_bhi_fc);
    cudaGetSymbolAddress((void**)&p_blo_fc, g_blo_fc);

    const int TB = 256;
    const int MT = (NN + 127)/128;   // 235

    // ---- CSR build ----
    zero_cnt_kernel<<<(NN+TB-1)/TB, TB>>>();
    hist_kernel<<<(EE+TB-1)/TB, TB>>>(ei);
    scan_kernel<<<1, 1024>>>();
    cursor_kernel<<<(NN+TB-1)/TB, TB>>>();
    fill_kernel<<<(EE+TB-1)/TB, TB>>>(ei);
    deg_kernel<<<(NN*32+TB-1)/TB, TB>>>(ew);

    // ---- weight conversions ----
    cvt_W_kernel<<<(192*FIN+TB-1)/TB, TB>>>(W_gcn, p_bhi_gcn, p_blo_gcn, FIN, HID, 192);
    cvt_Wfc_kernel<<<(192*264+TB-1)/TB, TB>>>(W_fc1, W_fc2);
    bias_fc_kernel<<<1, 160>>>(b_fc1, b_fc2, pro_bias);

    // ---- layer 0: GCN + relu ----
    hmma_gemm_kernel<<<dim3(3, MT), 256>>>(x, nullptr, p_bhi_gcn, p_blo_gcn, nullptr, p_h0, NN, HID, FIN);
    gcn_agg_kernel<<<NN, HID>>>(ew, b_gcn);

    // ---- layer 1: GAT + relu + gated fusion ----
    cvt_W_kernel<<<(576*HID+TB-1)/TB, TB>>>(W_gat1, p_bhi, p_blo, HID, HH, 576);
    hmma_gemm_kernel<<<dim3(9, MT), 256>>>(p_x1, nullptr, p_bhi, p_blo, nullptr, p_hg, NN, HH, HID);
    scores_kernel<<<NN, 128>>>(a_src1, a_dst1);
    exp_edge_kernel<<<(EE+TB-1)/TB, TB>>>(ei);
    gat_agg_kernel<<<NN, HID>>>(b_gat1, 1);
    hmma_gemm_kernel<<<dim3(3, MT), 256>>>(p_xc, p_x1, p_bhi_fc, p_blo_fc, p_bias_fc, p_t, NN, HID, 264);
    gate_kernel<<<(NN*HID+TB-1)/TB, TB>>>(p_x1, p_x2);

    // ---- layer 2: GAT (no relu) + gated fusion ----
    cvt_W_kernel<<<(576*HID+TB-1)/TB, TB>>>(W_gat2, p_bhi, p_blo, HID, HH, 576);
    hmma_gemm_kernel<<<dim3(9, MT), 256>>>(p_x2, nullptr, p_bhi, p_blo, nullptr, p_hg, NN, HH, HID);
    scores_kernel<<<NN, 128>>>(a_src2, a_dst2);
    exp_edge_kernel<<<(EE+TB-1)/TB, TB>>>(ei);
    gat_agg_kernel<<<NN, HID>>>(b_gat2, 0);
    hmma_gemm_kernel<<<dim3(3, MT), 256>>>(p_xc, p_x2, p_bhi_fc, p_blo_fc, p_bias_fc, p_t, NN, HID, 264);
    gate_kernel<<<(NN*HID+TB-1)/TB, TB>>>(p_x2, p_x3);

    // ---- pool + head ----
    pool_init_kernel<<<(GG*HID+TB-1)/TB, TB>>>();
    pool_max_kernel<<<(NN*HID+TB-1)/TB, TB>>>(batch);
    pool_decode_kernel<<<(GG*HID+TB-1)/TB, TB>>>();
    gemm_kernel<true ><<<gemm_grid(GG,GFC ), 256>>>(p_pool, W_g1, b_g1, p_hid, GG, GFC, HID);
    gemm_kernel<false><<<gemm_grid(GG,OUTD), 256>>>(p_hid, W_g2, b_g2, out, GG, OUTD, GFC);
}